// round 6
// baseline (speedup 1.0000x reference)
#include <cuda_runtime.h>

typedef unsigned long long ull;

#define TT   512
#define BB   256
#define DIN  85
#define HH   512
#define NOUT 33

constexpr size_t GSc = (size_t)TT * HH * BB;   // 67,108,864 elements per gate

// Scratch (allocation-free rule: __device__ globals)
__device__ float g_pre[4 * GSc];   // [gate][t][h][b]  (1.07 GB)
__device__ float g_hid[GSc];       // [t][h][b]        (268 MB)
__device__ unsigned g_cnt = 0;
__device__ volatile unsigned g_gen = 0;

// ---------- packed fp32x2 helpers ----------
__device__ __forceinline__ ull pack2(float x, float y) {
    ull v;
    asm("mov.b64 %0, {%1, %2};" : "=l"(v)
        : "r"(__float_as_uint(x)), "r"(__float_as_uint(y)));
    return v;
}
__device__ __forceinline__ float2 unpack2(ull v) {
    unsigned a, b;
    asm("mov.b64 {%0, %1}, %2;" : "=r"(a), "=r"(b) : "l"(v));
    return make_float2(__uint_as_float(a), __uint_as_float(b));
}
#define FMA2(acc, a, b) \
    asm("fma.rn.f32x2 %0, %1, %2, %0;" : "+l"(acc) : "l"(a), "l"(b))

// ---------- fast activations (rel err ~1e-6) ----------
__device__ __forceinline__ float sigf(float x) {
    x = fminf(fmaxf(x, -30.f), 30.f);
    return __fdividef(1.f, 1.f + __expf(-x));
}
__device__ __forceinline__ float tanh_fast(float x) {
    x = fminf(fmaxf(x, -15.f), 15.f);
    float e = __expf(-2.f * x);
    return __fdividef(1.f - e, 1.f + e);
}

// =====================================================================
// Phase 1: input projections  pre[g][t][h][b] = sum_i x[t,b,i] * Wxg[h,i]
// One CTA per t. x[t] staged transposed into SMEM as xs[i][b] (row stride
// 258 floats: even for 8B alignment, 258%32=2 so staging writes spread banks).
// =====================================================================
__global__ void __launch_bounds__(256, 1) k_input_proj(
    const float* __restrict__ x,
    const float* __restrict__ Wxi, const float* __restrict__ Wxf,
    const float* __restrict__ Wxo, const float* __restrict__ Wxc)
{
    extern __shared__ float xs[];          // [85][258]
    const int t = blockIdx.x;
    const float* xt = x + (size_t)t * BB * DIN;
    for (int idx = threadIdx.x; idx < BB * DIN; idx += 256) {
        int b = idx / DIN;
        int i = idx - b * DIN;
        xs[i * 258 + b] = xt[idx];
    }
    __syncthreads();

    const int warp = threadIdx.x >> 5;
    const int lane = threadIdx.x & 31;

    for (int r = warp; r < 4 * HH; r += 8) {
        const int g = r >> 9;
        const int h = r & (HH - 1);
        const float* wrow;
        if      (g == 0) wrow = Wxi + h * DIN;
        else if (g == 1) wrow = Wxf + h * DIN;
        else if (g == 2) wrow = Wxo + h * DIN;
        else             wrow = Wxc + h * DIN;

        ull a0 = 0, a1 = 0, a2 = 0, a3 = 0;   // 8 b-values per lane as 4 packs
#pragma unroll 5
        for (int i = 0; i < DIN; i++) {
            float w = __ldg(wrow + i);
            ull w2 = pack2(w, w);
            const ull* xr = (const ull*)(xs + i * 258);
            FMA2(a0, w2, xr[lane]);
            FMA2(a1, w2, xr[lane + 32]);
            FMA2(a2, w2, xr[lane + 64]);
            FMA2(a3, w2, xr[lane + 96]);
        }
        ull* pp = (ull*)(g_pre + (size_t)g * GSc + ((size_t)t * HH + h) * BB);
        pp[lane]      = a0;
        pp[lane + 32] = a1;
        pp[lane + 64] = a2;
        pp[lane + 96] = a3;
    }
}

// =====================================================================
// Phase 2: persistent recurrence. 128 CTAs (all resident), 256 threads.
// Warp task: one h (4 per CTA) x half of B (128 b). Lane owns 4 b values.
// Weights (4 h x 4 gates x 512 k) pre-duplicated {w,w} in 64KB SMEM.
// C state lives in registers. Grid barrier per step.
// =====================================================================
__device__ __forceinline__ void grid_sync_128()
{
    __threadfence();
    __syncthreads();
    if (threadIdx.x == 0) {
        unsigned oldg = g_gen;
        if (atomicAdd(&g_cnt, 1u) == gridDim.x - 1) {
            g_cnt = 0;
            __threadfence();
            g_gen = oldg + 1;
        } else {
            while (g_gen == oldg) { __nanosleep(32); }
        }
        __threadfence();
    }
    __syncthreads();
}

__global__ void __launch_bounds__(256, 1) k_lstm_rec(
    const float* __restrict__ Whi, const float* __restrict__ Whf,
    const float* __restrict__ Who, const float* __restrict__ Whc,
    const float* __restrict__ bhi, const float* __restrict__ bhf,
    const float* __restrict__ bho, const float* __restrict__ bhc)
{
    extern __shared__ ull s_w[];           // [4 h][4 gate][512 k] packed {w,w}
    const int warp  = threadIdx.x >> 5;
    const int lane  = threadIdx.x & 31;
    const int hl    = warp >> 1;           // 0..3
    const int h     = blockIdx.x * 4 + hl;
    const int bhalf = warp & 1;

    // one-time weight preload into SMEM
    for (int idx = threadIdx.x; idx < 4 * 4 * 512; idx += 256) {
        int k  = idx & 511;
        int g  = (idx >> 9) & 3;
        int hh = idx >> 11;
        int row = (blockIdx.x * 4 + hh) * HH + k;
        float w;
        if      (g == 0) w = Whi[row];
        else if (g == 1) w = Whf[row];
        else if (g == 2) w = Who[row];
        else             w = Whc[row];
        s_w[idx] = pack2(w, w);
    }
    __syncthreads();

    const ull* wr = s_w + hl * 2048;
    const int f2a = bhalf * 64 + lane;     // float2 index within B (128 pairs)
    const int f2b = f2a + 32;
    const float bi  = bhi[h], bf_ = bhf[h], bo = bho[h], bc = bhc[h];

    float C00 = 0.f, C01 = 0.f, C10 = 0.f, C11 = 0.f;

#pragma unroll 1
    for (int t = 0; t < TT; t++) {
        ull ai0 = 0, ai1 = 0, af0 = 0, af1 = 0;
        ull ao0 = 0, ao1 = 0, ac0 = 0, ac1 = 0;

        if (t > 0) {
            const ull* hp = (const ull*)(g_hid + (size_t)(t - 1) * HH * BB);
#pragma unroll 4
            for (int k = 0; k < HH; k++) {
                ull hv0 = hp[k * 128 + f2a];
                ull hv1 = hp[k * 128 + f2b];
                ull wi = wr[k];
                ull wf = wr[512  + k];
                ull wo = wr[1024 + k];
                ull wc = wr[1536 + k];
                FMA2(ai0, wi, hv0); FMA2(ai1, wi, hv1);
                FMA2(af0, wf, hv0); FMA2(af1, wf, hv1);
                FMA2(ao0, wo, hv0); FMA2(ao1, wo, hv1);
                FMA2(ac0, wc, hv0); FMA2(ac1, wc, hv1);
            }
        }

        const float* prebase = g_pre + ((size_t)t * HH + h) * BB;
        const float2* pi = (const float2*)(prebase);
        const float2* pf = (const float2*)(prebase + GSc);
        const float2* po = (const float2*)(prebase + 2 * GSc);
        const float2* pc = (const float2*)(prebase + 3 * GSc);

        float2 vi0 = unpack2(ai0), vi1 = unpack2(ai1);
        float2 vf0 = unpack2(af0), vf1 = unpack2(af1);
        float2 vo0 = unpack2(ao0), vo1 = unpack2(ao1);
        float2 vc0 = unpack2(ac0), vc1 = unpack2(ac1);

        float2 xi0 = pi[f2a], xi1 = pi[f2b];
        float2 xf0 = pf[f2a], xf1 = pf[f2b];
        float2 xo0 = po[f2a], xo1 = po[f2b];
        float2 xc0 = pc[f2a], xc1 = pc[f2b];

        float I, F, O, G;
        I = sigf(vi0.x + xi0.x + bi);  F = sigf(vf0.x + xf0.x + bf_);
        O = sigf(vo0.x + xo0.x + bo);  G = tanh_fast(vc0.x + xc0.x + bc);
        C00 = F * C00 + I * G;  float h0 = O * tanh_fast(C00);

        I = sigf(vi0.y + xi0.y + bi);  F = sigf(vf0.y + xf0.y + bf_);
        O = sigf(vo0.y + xo0.y + bo);  G = tanh_fast(vc0.y + xc0.y + bc);
        C01 = F * C01 + I * G;  float h1 = O * tanh_fast(C01);

        I = sigf(vi1.x + xi1.x + bi);  F = sigf(vf1.x + xf1.x + bf_);
        O = sigf(vo1.x + xo1.x + bo);  G = tanh_fast(vc1.x + xc1.x + bc);
        C10 = F * C10 + I * G;  float h2 = O * tanh_fast(C10);

        I = sigf(vi1.y + xi1.y + bi);  F = sigf(vf1.y + xf1.y + bf_);
        O = sigf(vo1.y + xo1.y + bo);  G = tanh_fast(vc1.y + xc1.y + bc);
        C11 = F * C11 + I * G;  float h3 = O * tanh_fast(C11);

        float2* op = (float2*)(g_hid + (size_t)t * HH * BB + (size_t)h * BB);
        op[f2a] = make_float2(h0, h1);
        op[f2b] = make_float2(h2, h3);

        grid_sync_128();
    }
}

// =====================================================================
// Phase 3: readout  out[t][b][o] = sum_h hid[t][h][b]*Wro[o][h] + bro[o]
// One CTA per t; warp = 32 b values; h processed in pairs via FFMA2.
// =====================================================================
__global__ void __launch_bounds__(256, 1) k_readout(
    const float* __restrict__ Wro, const float* __restrict__ bro,
    float* __restrict__ out)
{
    extern __shared__ float ws[];          // [33][512]
    for (int idx = threadIdx.x; idx < NOUT * HH; idx += 256)
        ws[idx] = Wro[idx];
    __syncthreads();

    const int warp = threadIdx.x >> 5;
    const int lane = threadIdx.x & 31;
    const int t = blockIdx.x;
    const int b = warp * 32 + lane;
    const float* hp = g_hid + (size_t)t * HH * BB + b;

    ull acc[NOUT];
#pragma unroll
    for (int o = 0; o < NOUT; o++) acc[o] = 0;

    for (int hh = 0; hh < HH; hh += 2) {
        float hv0 = hp[(size_t)hh * BB];
        float hv1 = hp[(size_t)(hh + 1) * BB];
        ull hv = pack2(hv0, hv1);
        const ull* wp = (const ull*)(ws + hh);   // ws[o*512+hh] pairs
#pragma unroll
        for (int o = 0; o < NOUT; o++)
            FMA2(acc[o], hv, wp[o * 256]);
    }

    float* op = out + ((size_t)t * BB + b) * NOUT;
#pragma unroll
    for (int o = 0; o < NOUT; o++) {
        float2 v = unpack2(acc[o]);
        op[o] = v.x + v.y + bro[o];
    }
}

// =====================================================================
extern "C" void kernel_launch(void* const* d_in, const int* in_sizes, int n_in,
                              void* d_out, int out_size)
{
    const float* x   = (const float*)d_in[0];
    const float* Wxi = (const float*)d_in[1];
    const float* Wxf = (const float*)d_in[2];
    const float* Wxo = (const float*)d_in[3];
    const float* Wxc = (const float*)d_in[4];
    const float* Whi = (const float*)d_in[5];
    const float* bhi = (const float*)d_in[6];
    const float* Whf = (const float*)d_in[7];
    const float* bhf = (const float*)d_in[8];
    const float* Who = (const float*)d_in[9];
    const float* bho = (const float*)d_in[10];
    const float* Whc = (const float*)d_in[11];
    const float* bhc = (const float*)d_in[12];
    const float* Wro = (const float*)d_in[13];
    const float* bro = (const float*)d_in[14];
    float* out = (float*)d_out;

    const int smem_p1 = 85 * 258 * 4;       // 87,720 B
    const int smem_p2 = 4 * 4 * 512 * 8;    // 65,536 B
    const int smem_p3 = NOUT * HH * 4;      // 67,584 B

    cudaFuncSetAttribute(k_input_proj, cudaFuncAttributeMaxDynamicSharedMemorySize, smem_p1);
    cudaFuncSetAttribute(k_lstm_rec,   cudaFuncAttributeMaxDynamicSharedMemorySize, smem_p2);
    cudaFuncSetAttribute(k_readout,    cudaFuncAttributeMaxDynamicSharedMemorySize, smem_p3);

    k_input_proj<<<TT, 256, smem_p1>>>(x, Wxi, Wxf, Wxo, Wxc);
    k_lstm_rec<<<128, 256, smem_p2>>>(Whi, Whf, Who, Whc, bhi, bhf, bho, bhc);
    k_readout<<<TT, 256, smem_p3>>>(Wro, bro, out);
}

// round 9
// speedup vs baseline: 1.8512x; 1.8512x over previous
#include <cuda_runtime.h>

typedef unsigned long long ull;

#define TT   512
#define BB   256
#define DIN  85
#define HH   512
#define NOUT 33

constexpr size_t GSc = (size_t)TT * HH * BB;   // elements per gate

// Scratch (allocation-free rule: __device__ globals)
__device__ float g_pre[4 * GSc];   // [gate][t][h][b]
__device__ float g_hid[GSc];       // [t][h][b]
__device__ unsigned g_cnt = 0;
__device__ volatile unsigned g_gen = 0;

// ---------- packed fp32x2 helpers ----------
__device__ __forceinline__ ull pack2(float x, float y) {
    ull v;
    asm("mov.b64 %0, {%1, %2};" : "=l"(v)
        : "r"(__float_as_uint(x)), "r"(__float_as_uint(y)));
    return v;
}
__device__ __forceinline__ float2 unpack2(ull v) {
    unsigned a, b;
    asm("mov.b64 {%0, %1}, %2;" : "=r"(a), "=r"(b) : "l"(v));
    return make_float2(__uint_as_float(a), __uint_as_float(b));
}
#define FMA2(acc, a, b) \
    asm("fma.rn.f32x2 %0, %1, %2, %0;" : "+l"(acc) : "l"(a), "l"(b))

// ---------- fast activations (validated rel err ~4e-7 final) ----------
__device__ __forceinline__ float sigf(float x) {
    x = fminf(fmaxf(x, -30.f), 30.f);
    return __fdividef(1.f, 1.f + __expf(-x));
}
__device__ __forceinline__ float tanh_fast(float x) {
    x = fminf(fmaxf(x, -15.f), 15.f);
    float e = __expf(-2.f * x);
    return __fdividef(1.f - e, 1.f + e);
}

// ---------- cp.async helpers ----------
__device__ __forceinline__ unsigned smem_u32(const void* p) {
    return (unsigned)__cvta_generic_to_shared(p);
}
__device__ __forceinline__ void cp16(unsigned dst, const void* src) {
    asm volatile("cp.async.cg.shared.global [%0], [%1], 16;" :: "r"(dst), "l"(src));
}
#define CP_COMMIT() asm volatile("cp.async.commit_group;")
template<int N> __device__ __forceinline__ void cp_wait() {
    asm volatile("cp.async.wait_group %0;" :: "n"(N));
}

// =====================================================================
// Phase 1: input projections  pre[g][t][h][b] = sum_i x[t,b,i] * Wxg[h,i]
// =====================================================================
__global__ void __launch_bounds__(256, 1) k_input_proj(
    const float* __restrict__ x,
    const float* __restrict__ Wxi, const float* __restrict__ Wxf,
    const float* __restrict__ Wxo, const float* __restrict__ Wxc)
{
    extern __shared__ float xs[];          // [85][258]
    const int t = blockIdx.x;
    const float* xt = x + (size_t)t * BB * DIN;
    for (int idx = threadIdx.x; idx < BB * DIN; idx += 256) {
        int b = idx / DIN;
        int i = idx - b * DIN;
        xs[i * 258 + b] = xt[idx];
    }
    __syncthreads();

    const int warp = threadIdx.x >> 5;
    const int lane = threadIdx.x & 31;

    for (int r = warp; r < 4 * HH; r += 8) {
        const int g = r >> 9;
        const int h = r & (HH - 1);
        const float* wrow;
        if      (g == 0) wrow = Wxi + h * DIN;
        else if (g == 1) wrow = Wxf + h * DIN;
        else if (g == 2) wrow = Wxo + h * DIN;
        else             wrow = Wxc + h * DIN;

        ull a0 = 0, a1 = 0, a2 = 0, a3 = 0;
#pragma unroll 5
        for (int i = 0; i < DIN; i++) {
            float w = __ldg(wrow + i);
            ull w2 = pack2(w, w);
            const ull* xr = (const ull*)(xs + i * 258);
            FMA2(a0, w2, xr[lane]);
            FMA2(a1, w2, xr[lane + 32]);
            FMA2(a2, w2, xr[lane + 64]);
            FMA2(a3, w2, xr[lane + 96]);
        }
        ull* pp = (ull*)(g_pre + (size_t)g * GSc + ((size_t)t * HH + h) * BB);
        pp[lane]      = a0;
        pp[lane + 32] = a1;
        pp[lane + 64] = a2;
        pp[lane + 96] = a3;
    }
}

// =====================================================================
// Phase 2: persistent recurrence, register/SMEM-tiled GEMM.
// 128 CTAs x 256 threads. CTA tile: 16 h (64 gate rows) x 64 b.
//   h_blk = blockIdx.x & 31  -> h0 = h_blk*16
//   b_blk = blockIdx.x >> 5  -> b0 = b_blk*64
// Thread: h_me = tid & 15 (one h, all 4 gates), bq = tid >> 4 (4 b values).
// SMEM: Ws[512 k][64 rows] fp32 (128 KB, resident) + Hs double buffer
//       2 x [128 k][64 b] (64 KB), filled via cp.async per step.
// =====================================================================
__device__ __forceinline__ void grid_sync_all()
{
    __threadfence();
    __syncthreads();
    if (threadIdx.x == 0) {
        unsigned oldg = g_gen;
        if (atomicAdd(&g_cnt, 1u) == gridDim.x - 1) {
            g_cnt = 0;
            __threadfence();
            g_gen = oldg + 1;
        } else {
            while (g_gen == oldg) { __nanosleep(32); }
        }
        __threadfence();
    }
    __syncthreads();
}

__global__ void __launch_bounds__(256, 1) k_lstm_rec(
    const float* __restrict__ Whi, const float* __restrict__ Whf,
    const float* __restrict__ Who, const float* __restrict__ Whc,
    const float* __restrict__ bhi, const float* __restrict__ bhf,
    const float* __restrict__ bho, const float* __restrict__ bhc)
{
    extern __shared__ float smem_f[];
    float* sWs = smem_f;                    // 32768 floats
    float* sHs = smem_f + 32768;            // 2 x 8192 floats
    const unsigned sHs_u32 = smem_u32(sHs);

    const int tid  = threadIdx.x;
    const int h_me = tid & 15;
    const int bq   = tid >> 4;              // 0..15
    const int h0   = (blockIdx.x & 31) * 16;
    const int b0   = (blockIdx.x >> 5) * 64;
    const int h    = h0 + h_me;
    const int bbase = b0 + bq * 4;

    // One-time W load: Ws[k*64 + hm*4 + g] = W_g[h0+hm][k]
    // (consecutive tid -> consecutive smem addr: conflict-free STS)
    for (int idx = tid; idx < 512 * 64; idx += 256) {
        int r  = idx & 63;          // row within k-slice
        int k  = idx >> 6;
        int hm = r >> 2;
        int g  = r & 3;
        int src = (h0 + hm) * HH + k;
        float w;
        if      (g == 0) w = Whi[src];
        else if (g == 1) w = Whf[src];
        else if (g == 2) w = Who[src];
        else             w = Whc[src];
        sWs[idx] = w;
    }
    const float bi  = bhi[h], bf_ = bhf[h], bo = bho[h], bc = bhc[h];
    float C0 = 0.f, C1 = 0.f, C2 = 0.f, C3 = 0.f;
    __syncthreads();

#pragma unroll 1
    for (int t = 0; t < TT; t++) {
        // Prefetch gate pre-activations (independent of Hs -> hidden by GEMM)
        const float* pb = g_pre + ((size_t)t * HH + h) * BB + bbase;
        float4 xi = *(const float4*)(pb);
        float4 xf = *(const float4*)(pb + GSc);
        float4 xo = *(const float4*)(pb + 2 * GSc);
        float4 xc = *(const float4*)(pb + 3 * GSc);

        ull aIF0 = 0, aIF1 = 0, aIF2 = 0, aIF3 = 0;
        ull aOC0 = 0, aOC1 = 0, aOC2 = 0, aOC3 = 0;

        if (t > 0) {
            const float* hsrc = g_hid + (size_t)(t - 1) * HH * BB + b0;

            // stage chunk 0 (k rows 0..127, 64 cols) into buffer 0
            {
                const float* src = hsrc;
#pragma unroll
                for (int j = 0; j < 8; j++) {
                    int i   = tid + j * 256;        // 0..2047
                    int row = i >> 4, col = i & 15;
                    cp16(sHs_u32 + (unsigned)i * 16, src + row * BB + col * 4);
                }
                CP_COMMIT();
            }

#pragma unroll 1
            for (int c = 0; c < 4; c++) {
                if (c < 3) {   // prefetch next chunk into the other buffer
                    const float* src = hsrc + (size_t)(c + 1) * 128 * BB;
                    unsigned dstb = sHs_u32 + (unsigned)(((c + 1) & 1) ? 32768 : 0);
#pragma unroll
                    for (int j = 0; j < 8; j++) {
                        int i   = tid + j * 256;
                        int row = i >> 4, col = i & 15;
                        cp16(dstb + (unsigned)i * 16, src + row * BB + col * 4);
                    }
                    CP_COMMIT();
                    cp_wait<1>();
                } else {
                    cp_wait<0>();
                }
                __syncthreads();

                const ulonglong2* wp2 =
                    (const ulonglong2*)sWs + (size_t)c * 2048 + h_me;
                const float4* hb4 =
                    (const float4*)(sHs + (c & 1) * 8192) + bq;

#pragma unroll 4
                for (int kk = 0; kk < 128; kk++) {
                    ulonglong2 w2 = wp2[kk * 16];      // {wI,wF},{wO,wC}
                    float4 hv = hb4[kk * 16];          // 4 b values
                    ull h0d = pack2(hv.x, hv.x);
                    ull h1d = pack2(hv.y, hv.y);
                    ull h2d = pack2(hv.z, hv.z);
                    ull h3d = pack2(hv.w, hv.w);
                    FMA2(aIF0, w2.x, h0d); FMA2(aOC0, w2.y, h0d);
                    FMA2(aIF1, w2.x, h1d); FMA2(aOC1, w2.y, h1d);
                    FMA2(aIF2, w2.x, h2d); FMA2(aOC2, w2.y, h2d);
                    FMA2(aIF3, w2.x, h3d); FMA2(aOC3, w2.y, h3d);
                }
                __syncthreads();
            }
        }

        // Epilogue: gates -> cell update -> hidden state
        float hv0, hv1, hv2, hv3;
        {
            float2 vIF = unpack2(aIF0), vOC = unpack2(aOC0);
            float I = sigf(vIF.x + xi.x + bi);
            float F = sigf(vIF.y + xf.x + bf_);
            float O = sigf(vOC.x + xo.x + bo);
            float G = tanh_fast(vOC.y + xc.x + bc);
            C0 = F * C0 + I * G;  hv0 = O * tanh_fast(C0);
        }
        {
            float2 vIF = unpack2(aIF1), vOC = unpack2(aOC1);
            float I = sigf(vIF.x + xi.y + bi);
            float F = sigf(vIF.y + xf.y + bf_);
            float O = sigf(vOC.x + xo.y + bo);
            float G = tanh_fast(vOC.y + xc.y + bc);
            C1 = F * C1 + I * G;  hv1 = O * tanh_fast(C1);
        }
        {
            float2 vIF = unpack2(aIF2), vOC = unpack2(aOC2);
            float I = sigf(vIF.x + xi.z + bi);
            float F = sigf(vIF.y + xf.z + bf_);
            float O = sigf(vOC.x + xo.z + bo);
            float G = tanh_fast(vOC.y + xc.z + bc);
            C2 = F * C2 + I * G;  hv2 = O * tanh_fast(C2);
        }
        {
            float2 vIF = unpack2(aIF3), vOC = unpack2(aOC3);
            float I = sigf(vIF.x + xi.w + bi);
            float F = sigf(vIF.y + xf.w + bf_);
            float O = sigf(vOC.x + xo.w + bo);
            float G = tanh_fast(vOC.y + xc.w + bc);
            C3 = F * C3 + I * G;  hv3 = O * tanh_fast(C3);
        }

        *(float4*)(g_hid + ((size_t)t * HH + h) * BB + bbase) =
            make_float4(hv0, hv1, hv2, hv3);

        if (t < TT - 1) grid_sync_all();
    }
}

// =====================================================================
// Phase 3: readout  out[t][b][o] = sum_h hid[t][h][b]*Wro[o][h] + bro[o]
// =====================================================================
__global__ void __launch_bounds__(256, 1) k_readout(
    const float* __restrict__ Wro, const float* __restrict__ bro,
    float* __restrict__ out)
{
    extern __shared__ float ws[];          // [33][512]
    for (int idx = threadIdx.x; idx < NOUT * HH; idx += 256)
        ws[idx] = Wro[idx];
    __syncthreads();

    const int warp = threadIdx.x >> 5;
    const int lane = threadIdx.x & 31;
    const int t = blockIdx.x;
    const int b = warp * 32 + lane;
    const float* hp = g_hid + (size_t)t * HH * BB + b;

    ull acc[NOUT];
#pragma unroll
    for (int o = 0; o < NOUT; o++) acc[o] = 0;

    for (int hh = 0; hh < HH; hh += 2) {
        float hv0 = hp[(size_t)hh * BB];
        float hv1 = hp[(size_t)(hh + 1) * BB];
        ull hv = pack2(hv0, hv1);
        const ull* wp = (const ull*)(ws + hh);
#pragma unroll
        for (int o = 0; o < NOUT; o++)
            FMA2(acc[o], hv, wp[o * 256]);
    }

    float* op = out + ((size_t)t * BB + b) * NOUT;
#pragma unroll
    for (int o = 0; o < NOUT; o++) {
        float2 v = unpack2(acc[o]);
        op[o] = v.x + v.y + bro[o];
    }
}

// =====================================================================
extern "C" void kernel_launch(void* const* d_in, const int* in_sizes, int n_in,
                              void* d_out, int out_size)
{
    const float* x   = (const float*)d_in[0];
    const float* Wxi = (const float*)d_in[1];
    const float* Wxf = (const float*)d_in[2];
    const float* Wxo = (const float*)d_in[3];
    const float* Wxc = (const float*)d_in[4];
    const float* Whi = (const float*)d_in[5];
    const float* bhi = (const float*)d_in[6];
    const float* Whf = (const float*)d_in[7];
    const float* bhf = (const float*)d_in[8];
    const float* Who = (const float*)d_in[9];
    const float* bho = (const float*)d_in[10];
    const float* Whc = (const float*)d_in[11];
    const float* bhc = (const float*)d_in[12];
    const float* Wro = (const float*)d_in[13];
    const float* bro = (const float*)d_in[14];
    float* out = (float*)d_out;

    const int smem_p1 = 85 * 258 * 4;               // 87,720 B
    const int smem_p2 = (32768 + 2 * 8192) * 4;     // 196,608 B
    const int smem_p3 = NOUT * HH * 4;              // 67,584 B

    cudaFuncSetAttribute(k_input_proj, cudaFuncAttributeMaxDynamicSharedMemorySize, smem_p1);
    cudaFuncSetAttribute(k_lstm_rec,   cudaFuncAttributeMaxDynamicSharedMemorySize, smem_p2);
    cudaFuncSetAttribute(k_readout,    cudaFuncAttributeMaxDynamicSharedMemorySize, smem_p3);

    k_input_proj<<<TT, 256, smem_p1>>>(x, Wxi, Wxf, Wxo, Wxc);
    k_lstm_rec<<<128, 256, smem_p2>>>(Whi, Whf, Who, Whc, bhi, bhf, bho, bhc);
    k_readout<<<TT, 256, smem_p3>>>(Wro, bro, out);
}